// round 16
// baseline (speedup 1.0000x reference)
#include <cuda_runtime.h>
#include <cuda_fp16.h>
#include <cstdint>
#include <cstring>

#define B_   4
#define L1_  1024
#define D_   256
#define H_   8
#define HD_  32
#define L_   4
#define L2_  21760
#define NQ_  (B_ * L1_)          // 4096
#define MV_  (B_ * L2_)          // 87040

// ---------------- scratch (static device memory; no allocs) ----------------
__device__ __half g_v16[(size_t)MV_ * D_];      // fp16 v = value @ Wv^T (44.5 MB)
__device__ float  g_qproj[(size_t)NQ_ * 256];   // [off | aw] fused projection
__device__ float  g_outpre[(size_t)NQ_ * D_];
__device__ float  g_moutpre[(size_t)NQ_ * D_];
__device__ __half g_Wvh[65536];                 // Wv fp16 (single pass)
__device__ __half g_Woh[65536], g_Wol[65536];   // Wo fp16 hi/lo
__device__ __half g_Wqh[65536], g_Wql[65536];   // [Wbox;Wattn] fp16 hi/lo
__device__ float  g_bq[256];                    // [bbox | battn]

// ===========================================================================
// helpers
// ===========================================================================
__device__ __forceinline__ uint32_t h2_bits(__half2 h) {
    uint32_t u;
    memcpy(&u, &h, 4);
    return u;
}
__device__ __forceinline__ __half2 bits_h2(uint32_t u) {
    __half2 h;
    memcpy(&h, &u, 4);
    return h;
}
__device__ __forceinline__ uint32_t smem_u32(const void* p) {
    uint32_t a;
    asm("{ .reg .u64 t; cvta.to.shared.u64 t, %1; cvt.u32.u64 %0, t; }"
        : "=r"(a) : "l"(p));
    return a;
}
__device__ __forceinline__ void ldmx4(uint32_t addr, uint32_t& r0, uint32_t& r1,
                                      uint32_t& r2, uint32_t& r3) {
    asm volatile("ldmatrix.sync.aligned.m8n8.x4.shared.b16 {%0,%1,%2,%3}, [%4];"
                 : "=r"(r0), "=r"(r1), "=r"(r2), "=r"(r3) : "r"(addr));
}
__device__ __forceinline__ void mma16816(float* d, const uint32_t* a,
                                         const uint32_t* b) {
    asm volatile("mma.sync.aligned.m16n8k16.row.col.f32.f16.f16.f32 "
                 "{%0,%1,%2,%3}, {%4,%5,%6,%7}, {%8,%9}, {%0,%1,%2,%3};"
                 : "+f"(d[0]), "+f"(d[1]), "+f"(d[2]), "+f"(d[3])
                 : "r"(a[0]), "r"(a[1]), "r"(a[2]), "r"(a[3]),
                   "r"(b[0]), "r"(b[1]));
}
#define CP_ASYNC16(dst, src) \
    asm volatile("cp.async.cg.shared.global [%0], [%1], 16;" :: "r"(dst), "l"(src))
#define CP_COMMIT() asm volatile("cp.async.commit_group;" ::: "memory")
#define CP_WAIT0()  asm volatile("cp.async.wait_group 0;" ::: "memory")

// ---------------------------------------------------------------------------
// prep: weights -> fp16 (Wv single, Wo/[Wbox;Wattn] hi/lo); bias pack
// ---------------------------------------------------------------------------
__global__ void prep_w_kernel(const float* __restrict__ Wv,
                              const float* __restrict__ Wo,
                              const float* __restrict__ Wbox,
                              const float* __restrict__ Wattn,
                              const float* __restrict__ bbox,
                              const float* __restrict__ battn)
{
    int i = blockIdx.x * blockDim.x + threadIdx.x;   // 0..65535
    g_Wvh[i] = __float2half_rn(Wv[i]);
    float o = Wo[i];
    __half ho = __float2half_rn(o);
    g_Woh[i] = ho;
    g_Wol[i] = __float2half_rn(o - __half2float(ho));
    int r = i >> 8, c = i & 255;
    float q = (r < 128) ? Wbox[r * 256 + c] : Wattn[(r - 128) * 256 + c];
    __half hq = __float2half_rn(q);
    g_Wqh[i] = hq;
    g_Wql[i] = __float2half_rn(q - __half2float(hq));
    if (i < 256) g_bq[i] = (i < 128) ? bbox[i] : battn[i - 128];
}

// ===========================================================================
// Value GEMM (persistent CTAs): 136 CTAs x 5 tiles; W resident (128KB, once
// per CTA); A fp32 -> fp16 fused staging, distance-2 prefetch, 3x8KB bufs.
// smem = 131072 + 24576 + 1024 = 156672 B
// ===========================================================================
#define VW_SZ     131072
#define VA_BUF    8192
#define V_CTAS    136
#define V_TILES   (MV_ / 128)     // 680
__global__ __launch_bounds__(512)
void hmma_gemm_v(const float* __restrict__ A,
                 const __half* __restrict__ Wh,
                 const float* __restrict__ bias,
                 __half* __restrict__ C,
                 const unsigned char* __restrict__ mask)
{
    extern __shared__ __align__(16) unsigned char dsm[];
    float* bias_s = (float*)(dsm + VW_SZ + 3 * VA_BUF);

    const int t    = threadIdx.x;
    const int wid  = t >> 5;
    const int lane = t & 31;
    const int wm   = wid & 3;
    const int wn   = wid >> 2;
    const uint32_t base  = smem_u32(dsm);
    const uint32_t abase = base + VW_SZ;

    if (t < 256) bias_s[t] = bias[t];

    // ---- W prologue: once per CTA ----
#pragma unroll
    for (int u = 0; u < 16; u++) {
        int f  = t + u * 512;
        int r  = f >> 5;
        int j  = f & 31;
        int ch = j >> 2;
        int cu = j & 3;
        uint32_t dst = base + ch * 16384 + r * 64 + ((cu ^ ((r >> 1) & 3)) * 16);
        CP_ASYNC16(dst, Wh + (size_t)r * 256 + j * 8);
    }
    CP_COMMIT();
    CP_WAIT0();
    __syncthreads();

    const int ar = t >> 2;
    const int au = t & 3;
    const uint32_t asw = ((au ^ ((ar >> 1) & 3)) * 16) + ar * 64;

#pragma unroll 1
    for (int tile = blockIdx.x; tile < V_TILES; tile += V_CTAS) {
        const int m0 = tile * 128;
        const float* asrc = A + (size_t)(m0 + ar) * 256 + au * 8;

        float acc[2][8][4];
#pragma unroll
        for (int mt = 0; mt < 2; mt++)
#pragma unroll
            for (int nt = 0; nt < 8; nt++)
#pragma unroll
                for (int i = 0; i < 4; i++) acc[mt][nt][i] = 0.f;

        // two alternating prefetch register sets: pf[0] even chunks, pf[1] odd
        float4 pfa[2], pfb[2];

        // chunk 0 -> buf0 (STS now), chunk 1 -> regs (STS at iter 0)
        pfa[0] = *(const float4*)(asrc);
        pfb[0] = *(const float4*)(asrc + 4);
        {
            uint4 u;
            u.x = h2_bits(__floats2half2_rn(pfa[0].x, pfa[0].y));
            u.y = h2_bits(__floats2half2_rn(pfa[0].z, pfa[0].w));
            u.z = h2_bits(__floats2half2_rn(pfb[0].x, pfb[0].y));
            u.w = h2_bits(__floats2half2_rn(pfb[0].z, pfb[0].w));
            *(uint4*)(dsm + VW_SZ + asw) = u;
        }
        pfa[1] = *(const float4*)(asrc + 32);
        pfb[1] = *(const float4*)(asrc + 36);
        __syncthreads();

#pragma unroll
        for (int ch = 0; ch < 8; ch++) {
            // LDG chunk ch+2 into the set that held chunk ch (same parity)
            if (ch + 2 < 8) {
                pfa[ch & 1] = *(const float4*)(asrc + (ch + 2) * 32);
                pfb[ch & 1] = *(const float4*)(asrc + (ch + 2) * 32 + 4);
            }
            // STS chunk ch+1 (held in set (ch+1)&1) into buf[(ch+1)%3]
            if (ch + 1 < 8) {
                int ps = (ch + 1) & 1;
                uint4 u;
                u.x = h2_bits(__floats2half2_rn(pfa[ps].x, pfa[ps].y));
                u.y = h2_bits(__floats2half2_rn(pfa[ps].z, pfa[ps].w));
                u.z = h2_bits(__floats2half2_rn(pfb[ps].x, pfb[ps].y));
                u.w = h2_bits(__floats2half2_rn(pfb[ps].z, pfb[ps].w));
                *(uint4*)(dsm + VW_SZ + ((ch + 1) % 3) * VA_BUF + asw) = u;
            }

            const uint32_t uA = abase + (ch % 3) * VA_BUF;
            const uint32_t uB = base + ch * 16384;

#pragma unroll
            for (int s = 0; s < 2; s++) {
                uint32_t ah[2][4];
#pragma unroll
                for (int mt = 0; mt < 2; mt++) {
                    int row  = wm * 32 + mt * 16 + (lane & 15);
                    int unit = s * 2 + (lane >> 4);
                    ldmx4(uA + row * 64 + (unit ^ ((row >> 1) & 3)) * 16,
                          ah[mt][0], ah[mt][1], ah[mt][2], ah[mt][3]);
                }
#pragma unroll
                for (int half = 0; half < 2; half++) {
                    uint32_t bh[4][2];
#pragma unroll
                    for (int p = 0; p < 2; p++) {
                        int pp   = half * 2 + p;
                        int nrow = wn * 64 + pp * 16 + (lane & 7) + (((lane >> 4) & 1) << 3);
                        int unit = s * 2 + ((lane >> 3) & 1);
                        uint32_t off = nrow * 64 + (unit ^ ((nrow >> 1) & 3)) * 16;
                        ldmx4(uB + off, bh[p*2][0], bh[p*2][1], bh[p*2+1][0], bh[p*2+1][1]);
                    }
#pragma unroll
                    for (int mt = 0; mt < 2; mt++)
#pragma unroll
                        for (int q = 0; q < 4; q++)
                            mma16816(acc[mt][half * 4 + q], ah[mt], bh[q]);
                }
            }
            __syncthreads();
        }

        // epilogue: bias + mask, fp16 stores
        const int rw = lane >> 2;
        const int cw = (lane & 3) * 2;
#pragma unroll
        for (int mt = 0; mt < 2; mt++) {
            int r = m0 + wm * 32 + mt * 16 + rw;
            bool z0 = mask[r] != 0;
            bool z1 = mask[r + 8] != 0;
#pragma unroll
            for (int nt = 0; nt < 8; nt++) {
                int cl = wn * 64 + nt * 8 + cw;
                float b0 = bias_s[cl], b1 = bias_s[cl + 1];
                __half2 v0 = __floats2half2_rn(z0 ? 0.f : acc[mt][nt][0] + b0,
                                               z0 ? 0.f : acc[mt][nt][1] + b1);
                __half2 v1 = __floats2half2_rn(z1 ? 0.f : acc[mt][nt][2] + b0,
                                               z1 ? 0.f : acc[mt][nt][3] + b1);
                *(__half2*)(C + (size_t)r * 256 + cl)       = v0;
                *(__half2*)(C + (size_t)(r + 8) * 256 + cl) = v1;
            }
        }
        __syncthreads();
    }
}

// ===========================================================================
// fp32-A 2-pass HMMA GEMM (q-projection, out/mout): C[M,256] fp32.
// ===========================================================================
__global__ __launch_bounds__(512)
void hmma_gemm_fp16(const float* __restrict__ A0,
                    const float* __restrict__ A1,
                    const __half* __restrict__ Wh,
                    const __half* __restrict__ Wl,
                    const float* __restrict__ bias,
                    float* __restrict__ C0,
                    float* __restrict__ C1)
{
    __shared__ __align__(16) unsigned char smA [128 * 64];
    __shared__ __align__(16) unsigned char smBh[256 * 64];
    __shared__ __align__(16) unsigned char smBl[256 * 64];
    __shared__ float bias_s[256];

    const float* A = blockIdx.y ? A1 : A0;
    float*       C = blockIdx.y ? C1 : C0;

    const int t    = threadIdx.x;
    const int wid  = t >> 5;
    const int lane = t & 31;
    const int wm   = wid & 3;
    const int wn   = wid >> 2;
    const int m0   = blockIdx.x * 128;

    if (t < 256) bias_s[t] = bias[t];

    float acc[2][8][4];
#pragma unroll
    for (int mt = 0; mt < 2; mt++)
#pragma unroll
        for (int nt = 0; nt < 8; nt++)
#pragma unroll
            for (int i = 0; i < 4; i++) acc[mt][nt][i] = 0.f;

    const uint32_t uA  = smem_u32(smA);
    const uint32_t uBh = smem_u32(smBh);
    const uint32_t uBl = smem_u32(smBl);

    for (int k0 = 0; k0 < 256; k0 += 32) {
        {
            int r  = t >> 2;
            int c4 = t & 3;
            const float* src = A + (size_t)(m0 + r) * 256 + k0 + c4 * 8;
            float4 v0 = *(const float4*)(src);
            float4 v1 = *(const float4*)(src + 4);
            uint4 u;
            u.x = h2_bits(__floats2half2_rn(v0.x, v0.y));
            u.y = h2_bits(__floats2half2_rn(v0.z, v0.w));
            u.z = h2_bits(__floats2half2_rn(v1.x, v1.y));
            u.w = h2_bits(__floats2half2_rn(v1.z, v1.w));
            *(uint4*)(smA + r * 64 + (c4 ^ ((r >> 1) & 3)) * 16) = u;
        }
#pragma unroll
        for (int u = 0; u < 2; u++) {
            int f   = t + u * 512;
            int r   = f >> 2;
            int c16 = f & 3;
            uint32_t dst = r * 64 + (c16 ^ ((r >> 1) & 3)) * 16;
            *(uint4*)(smBh + dst) = *(const uint4*)(Wh + (size_t)r * 256 + k0 + c16 * 8);
            *(uint4*)(smBl + dst) = *(const uint4*)(Wl + (size_t)r * 256 + k0 + c16 * 8);
        }
        __syncthreads();

#pragma unroll
        for (int s = 0; s < 2; s++) {
            uint32_t ah[2][4];
#pragma unroll
            for (int mt = 0; mt < 2; mt++) {
                int row  = wm * 32 + mt * 16 + (lane & 15);
                int unit = s * 2 + (lane >> 4);
                ldmx4(uA + row * 64 + (unit ^ ((row >> 1) & 3)) * 16,
                      ah[mt][0], ah[mt][1], ah[mt][2], ah[mt][3]);
            }
#pragma unroll
            for (int half = 0; half < 2; half++) {
                uint32_t bh[4][2], bl[4][2];
#pragma unroll
                for (int p = 0; p < 2; p++) {
                    int pp   = half * 2 + p;
                    int nrow = wn * 64 + pp * 16 + (lane & 7) + (((lane >> 4) & 1) << 3);
                    int unit = s * 2 + ((lane >> 3) & 1);
                    uint32_t off = nrow * 64 + (unit ^ ((nrow >> 1) & 3)) * 16;
                    ldmx4(uBh + off, bh[p*2][0], bh[p*2][1], bh[p*2+1][0], bh[p*2+1][1]);
                    ldmx4(uBl + off, bl[p*2][0], bl[p*2][1], bl[p*2+1][0], bl[p*2+1][1]);
                }
#pragma unroll
                for (int mt = 0; mt < 2; mt++)
#pragma unroll
                    for (int q = 0; q < 4; q++) {
                        int nt = half * 4 + q;
                        mma16816(acc[mt][nt], ah[mt], bh[q]);
                        mma16816(acc[mt][nt], ah[mt], bl[q]);
                    }
            }
        }
        __syncthreads();
    }

    const int rw = lane >> 2;
    const int cw = (lane & 3) * 2;
#pragma unroll
    for (int mt = 0; mt < 2; mt++) {
        int r = m0 + wm * 32 + mt * 16 + rw;
#pragma unroll
        for (int nt = 0; nt < 8; nt++) {
            int cl = wn * 64 + nt * 8 + cw;
            float b0 = bias_s[cl], b1 = bias_s[cl + 1];
            float2 v0 = make_float2(acc[mt][nt][0] + b0, acc[mt][nt][1] + b1);
            float2 v1 = make_float2(acc[mt][nt][2] + b0, acc[mt][nt][3] + b1);
            *(float2*)(C + (size_t)r * 256 + cl)       = v0;
            *(float2*)(C + (size_t)(r + 8) * 256 + cl) = v1;
        }
    }
}

// ---------------------------------------------------------------------------
// Sampler v4 (passing R15): 4 samples/iteration, LDG.64 gather lanes.
// ---------------------------------------------------------------------------
__global__ __launch_bounds__(256)
void sample_kernel(const float* __restrict__ refwin,
                   float* __restrict__ awout)
{
    __shared__ float  sh_raw[128];
    __shared__ float  sh_off[128];
    __shared__ float2 sh_swlw[H_][64];
    __shared__ int4   sh_idx[512];
    __shared__ float4 sh_w[512];

    const int bq   = blockIdx.x;
    const int b    = bq >> 10;
    const int t    = threadIdx.x;
    const int h    = t >> 5;
    const int lane = t & 31;

    if (t < 128) sh_off[t] = g_qproj[(size_t)bq * 256 + t];
    else         sh_raw[t - 128] = g_qproj[(size_t)bq * 256 + t];
    __syncthreads();

    // ---- softmaxes (warp = head) ----
    float e[2];
    int   aidx[2];
#pragma unroll
    for (int tgt = 0; tgt < 2; tgt++) {
        int n = lane + 32 * tgt;
        int l = n >> 4, kk = n & 15, ii = kk >> 2, jj = kk & 3;
        int a = ((ii >> 1) << 1) + (jj >> 1);
        aidx[tgt] = a;
        e[tgt] = sh_raw[h * 16 + l * 4 + a];
    }
    awout[(size_t)bq * 512 + h * 64 + lane]      = e[0];
    awout[(size_t)bq * 512 + h * 64 + lane + 32] = e[1];

    float m = fmaxf(e[0], e[1]);
#pragma unroll
    for (int o = 16; o > 0; o >>= 1) m = fmaxf(m, __shfl_xor_sync(0xffffffffu, m, o));
    float p0 = __expf(e[0] - m), p1 = __expf(e[1] - m);
    float s = p0 + p1;
#pragma unroll
    for (int o = 16; o > 0; o >>= 1) s += __shfl_xor_sync(0xffffffffu, s, o);
    float inv = 1.f / s;

#pragma unroll
    for (int tgt = 0; tgt < 2; tgt++) {
        int a = aidx[tgt];
        float r0 = sh_raw[h * 16 + 0 + a], r1 = sh_raw[h * 16 + 4 + a];
        float r2 = sh_raw[h * 16 + 8 + a], r3 = sh_raw[h * 16 + 12 + a];
        float m4 = fmaxf(fmaxf(r0, r1), fmaxf(r2, r3));
        float s4 = __expf(r0 - m4) + __expf(r1 - m4) + __expf(r2 - m4) + __expf(r3 - m4);
        float lw = __expf(e[tgt] - m4) / s4;
        float sw = (tgt == 0 ? p0 : p1) * inv;
        sh_swlw[h][lane + 32 * tgt] = make_float2(sw, lw);
    }

    // ---- phase 1: per-sample indices (half2 units, +head offset) + weights
    const float rcx = refwin[bq * 4 + 0];
    const float rcy = refwin[bq * 4 + 1];
    const float rsx = refwin[bq * 4 + 2];
    const float rsy = refwin[bq * 4 + 3];

#pragma unroll
    for (int rep = 0; rep < 2; rep++) {
        int sidx = t + rep * 256;
        int hh = sidx >> 6;
        int n  = sidx & 63;
        int l  = n >> 4;
        int ii = (n >> 2) & 3;
        int jj = n & 3;

        float o0 = sh_off[hh * 16 + l * 4 + 0];
        float o1 = sh_off[hh * 16 + l * 4 + 1];
        float o2 = sh_off[hh * 16 + l * 4 + 2];
        float o3 = sh_off[hh * 16 + l * 4 + 3];
        float cx = rcx + o0 * 0.125f * rsx;
        float cy = rcy + o1 * 0.125f * rsy;
        float sx = fmaxf(rsx + o2 * 0.125f * rsx, 0.f);
        float sy = fmaxf(rsy + o3 * 0.125f * rsy, 0.f);

        int   Wl  = 128 >> l;
        float fW  = (float)Wl;
        int base  = (l == 0) ? 0 : (l == 1) ? 16384 : (l == 2) ? 20480 : 21504;

        float y   = (cy + ((float)ii - 1.5f) * 0.25f * sy) * fW - 0.5f;
        float x   = (cx + ((float)jj - 1.5f) * 0.25f * sx) * fW - 0.5f;
        float y0f = floorf(y);
        float x0f = floorf(x);
        float fy  = y - y0f;
        float fx  = x - x0f;
        int y0 = (int)y0f;
        int x0 = (int)x0f;
        bool vy0 = (y0 >= 0) && (y0 < Wl);
        bool vy1 = (y0 >= -1) && (y0 < Wl - 1);
        bool vx0 = (x0 >= 0) && (x0 < Wl);
        bool vx1 = (x0 >= -1) && (x0 < Wl - 1);
        int cy0 = min(max(y0, 0), Wl - 1);
        int cy1 = min(max(y0 + 1, 0), Wl - 1);
        int cx0 = min(max(x0, 0), Wl - 1);
        int cx1 = min(max(x0 + 1, 0), Wl - 1);

        int hofs = hh * 16;           // head offset in half2 units
        int4 id;
        id.x = (base + cy0 * Wl + cx0) * 128 + hofs;
        id.y = (base + cy0 * Wl + cx1) * 128 + hofs;
        id.z = (base + cy1 * Wl + cx0) * 128 + hofs;
        id.w = (base + cy1 * Wl + cx1) * 128 + hofs;
        float4 w;
        w.x = (vx0 && vy0) ? (1.f - fx) * (1.f - fy) : 0.f;
        w.y = (vx1 && vy0) ? fx * (1.f - fy) : 0.f;
        w.z = (vx0 && vy1) ? (1.f - fx) * fy : 0.f;
        w.w = (vx1 && vy1) ? fx * fy : 0.f;
        sh_idx[sidx] = id;
        sh_w[sidx]   = w;
    }
    __syncthreads();

    // ---- phase 2: 4 samples per iteration, 8B loads (4 channels/lane) ----
    const int sp2 = lane >> 3;      // sample subgroup 0..3
    const int lo  = lane & 7;       // 4-channel slot (2 half2)
    const __half2* vp = (const __half2*)g_v16 + (size_t)b * (L2_ * 128) + lo * 2;

    float4 ao = make_float4(0.f, 0.f, 0.f, 0.f);
    float4 am = make_float4(0.f, 0.f, 0.f, 0.f);

#pragma unroll 4
    for (int n = 0; n < 64; n += 4) {
        int4   id = sh_idx[h * 64 + n + sp2];
        float4 w  = sh_w[h * 64 + n + sp2];

        uint2 u0 = *(const uint2*)(vp + id.x);
        uint2 u1 = *(const uint2*)(vp + id.y);
        uint2 u2 = *(const uint2*)(vp + id.z);
        uint2 u3 = *(const uint2*)(vp + id.w);

        float2 a0 = __half22float2(bits_h2(u0.x));
        float2 b0 = __half22float2(bits_h2(u0.y));
        float2 a1 = __half22float2(bits_h2(u1.x));
        float2 b1 = __half22float2(bits_h2(u1.y));
        float2 a2 = __half22float2(bits_h2(u2.x));
        float2 b2 = __half22float2(bits_h2(u2.y));
        float2 a3 = __half22float2(bits_h2(u3.x));
        float2 b3 = __half22float2(bits_h2(u3.y));

        float c0 = w.x * a0.x + w.y * a1.x + w.z * a2.x + w.w * a3.x;
        float c1 = w.x * a0.y + w.y * a1.y + w.z * a2.y + w.w * a3.y;
        float c2 = w.x * b0.x + w.y * b1.x + w.z * b2.x + w.w * b3.x;
        float c3 = w.x * b0.y + w.y * b1.y + w.z * b2.y + w.w * b3.y;

        float2 sl = sh_swlw[h][n + sp2];
        ao.x += sl.x * c0;  ao.y += sl.x * c1;
        ao.z += sl.x * c2;  ao.w += sl.x * c3;
        am.x += sl.y * c0;  am.y += sl.y * c1;
        am.z += sl.y * c2;  am.w += sl.y * c3;
    }

    // reduce across the 4 sample subgroups (xor 8, then xor 16)
#pragma unroll
    for (int o = 8; o <= 16; o <<= 1) {
        ao.x += __shfl_xor_sync(0xffffffffu, ao.x, o);
        ao.y += __shfl_xor_sync(0xffffffffu, ao.y, o);
        ao.z += __shfl_xor_sync(0xffffffffu, ao.z, o);
        ao.w += __shfl_xor_sync(0xffffffffu, ao.w, o);
        am.x += __shfl_xor_sync(0xffffffffu, am.x, o);
        am.y += __shfl_xor_sync(0xffffffffu, am.y, o);
        am.z += __shfl_xor_sync(0xffffffffu, am.z, o);
        am.w += __shfl_xor_sync(0xffffffffu, am.w, o);
    }

    if (sp2 == 0) {
        size_t od = (size_t)bq * D_ + h * HD_ + lo * 4;
        *(float4*)(g_outpre  + od) = ao;
        *(float4*)(g_moutpre + od) = am;
    }
}

// ---------------------------------------------------------------------------
extern "C" void kernel_launch(void* const* d_in, const int* in_sizes, int n_in,
                              void* d_out, int out_size)
{
    const float* query = (const float*)d_in[0];
    const float* value = (const float*)d_in[1];
    const float* refw  = (const float*)d_in[2];
    const float* Wv    = (const float*)d_in[3];
    const float* bv    = (const float*)d_in[4];
    const float* Wo    = (const float*)d_in[5];
    const float* bo    = (const float*)d_in[6];
    const float* Wbox  = (const float*)d_in[7];
    const float* bbox  = (const float*)d_in[8];
    const float* Wattn = (const float*)d_in[9];
    const float* battn = (const float*)d_in[10];
    const unsigned char* vmask = (const unsigned char*)d_in[13];

    float* out   = (float*)d_out;
    float* mout  = out  + (size_t)NQ_ * D_;
    float* awout = mout + (size_t)NQ_ * D_;

    float *pqp, *pop, *pmp, *pbq;
    __half *pv16, *pwvh, *pwoh, *pwol, *pwqh, *pwql;
    cudaGetSymbolAddress((void**)&pv16,   g_v16);
    cudaGetSymbolAddress((void**)&pqp,    g_qproj);
    cudaGetSymbolAddress((void**)&pop,    g_outpre);
    cudaGetSymbolAddress((void**)&pmp,    g_moutpre);
    cudaGetSymbolAddress((void**)&pwvh,   g_Wvh);
    cudaGetSymbolAddress((void**)&pwoh,   g_Woh);
    cudaGetSymbolAddress((void**)&pwol,   g_Wol);
    cudaGetSymbolAddress((void**)&pwqh,   g_Wqh);
    cudaGetSymbolAddress((void**)&pwql,   g_Wql);
    cudaGetSymbolAddress((void**)&pbq,    g_bq);

    const int VSMEM = VW_SZ + 3 * VA_BUF + 1024;   // 156672
    cudaFuncSetAttribute(hmma_gemm_v,
                         cudaFuncAttributeMaxDynamicSharedMemorySize, VSMEM);

    // 0) prep: weights -> fp16
    prep_w_kernel<<<256, 256>>>(Wv, Wo, Wbox, Wattn, bbox, battn);
    // 1) fused q projection
    hmma_gemm_fp16<<<dim3(NQ_ / 128, 1), 512>>>(query, query, pwqh, pwql, pbq,
                                                pqp, pqp);
    // 2) v = value @ Wv^T + bv (persistent CTAs, distance-2 A prefetch)
    hmma_gemm_v<<<V_CTAS, 512, VSMEM>>>(value, pwvh, bv, pv16, vmask);
    // 3) softmaxes + sampling
    sample_kernel<<<NQ_, 256>>>(refw, awout);
    // 4) out + mout projections (fused, one launch)
    hmma_gemm_fp16<<<dim3(NQ_ / 128, 2), 512>>>(pop, pmp, pwoh, pwol, bo,
                                                out, mout);
}

// round 17
// speedup vs baseline: 1.0475x; 1.0475x over previous
#include <cuda_runtime.h>
#include <cuda_fp16.h>
#include <cstdint>
#include <cstring>

#define B_   4
#define L1_  1024
#define D_   256
#define H_   8
#define HD_  32
#define L_   4
#define L2_  21760
#define NQ_  (B_ * L1_)          // 4096
#define MV_  (B_ * L2_)          // 87040

// ---------------- scratch (static device memory; no allocs) ----------------
__device__ __half g_v16[(size_t)MV_ * D_];      // fp16 v = value @ Wv^T (44.5 MB)
__device__ float  g_qproj[(size_t)NQ_ * 256];   // [off | aw] fused projection
__device__ float  g_outpre[(size_t)NQ_ * D_];
__device__ float  g_moutpre[(size_t)NQ_ * D_];
__device__ __half g_Wvh[65536];                 // Wv fp16 (single pass)
__device__ __half g_Woh[65536];                 // Wo fp16 (single pass)
__device__ __half g_Wqh[65536], g_Wql[65536];   // [Wbox;Wattn] fp16 hi/lo
__device__ float  g_bq[256];                    // [bbox | battn]

// ===========================================================================
// helpers
// ===========================================================================
__device__ __forceinline__ uint32_t h2_bits(__half2 h) {
    uint32_t u;
    memcpy(&u, &h, 4);
    return u;
}
__device__ __forceinline__ __half2 bits_h2(uint32_t u) {
    __half2 h;
    memcpy(&h, &u, 4);
    return h;
}
__device__ __forceinline__ uint32_t smem_u32(const void* p) {
    uint32_t a;
    asm("{ .reg .u64 t; cvta.to.shared.u64 t, %1; cvt.u32.u64 %0, t; }"
        : "=r"(a) : "l"(p));
    return a;
}
__device__ __forceinline__ void ldmx4(uint32_t addr, uint32_t& r0, uint32_t& r1,
                                      uint32_t& r2, uint32_t& r3) {
    asm volatile("ldmatrix.sync.aligned.m8n8.x4.shared.b16 {%0,%1,%2,%3}, [%4];"
                 : "=r"(r0), "=r"(r1), "=r"(r2), "=r"(r3) : "r"(addr));
}
__device__ __forceinline__ void mma16816(float* d, const uint32_t* a,
                                         const uint32_t* b) {
    asm volatile("mma.sync.aligned.m16n8k16.row.col.f32.f16.f16.f32 "
                 "{%0,%1,%2,%3}, {%4,%5,%6,%7}, {%8,%9}, {%0,%1,%2,%3};"
                 : "+f"(d[0]), "+f"(d[1]), "+f"(d[2]), "+f"(d[3])
                 : "r"(a[0]), "r"(a[1]), "r"(a[2]), "r"(a[3]),
                   "r"(b[0]), "r"(b[1]));
}
#define CP_ASYNC16(dst, src) \
    asm volatile("cp.async.cg.shared.global [%0], [%1], 16;" :: "r"(dst), "l"(src))
#define CP_COMMIT() asm volatile("cp.async.commit_group;" ::: "memory")
#define CP_WAIT0()  asm volatile("cp.async.wait_group 0;" ::: "memory")

// ---------------------------------------------------------------------------
// prep: weights -> fp16 (Wv/Wo single, [Wbox;Wattn] hi/lo); bias pack
// ---------------------------------------------------------------------------
__global__ void prep_w_kernel(const float* __restrict__ Wv,
                              const float* __restrict__ Wo,
                              const float* __restrict__ Wbox,
                              const float* __restrict__ Wattn,
                              const float* __restrict__ bbox,
                              const float* __restrict__ battn)
{
    int i = blockIdx.x * blockDim.x + threadIdx.x;   // 0..65535
    g_Wvh[i] = __float2half_rn(Wv[i]);
    g_Woh[i] = __float2half_rn(Wo[i]);
    int r = i >> 8, c = i & 255;
    float q = (r < 128) ? Wbox[r * 256 + c] : Wattn[(r - 128) * 256 + c];
    __half hq = __float2half_rn(q);
    g_Wqh[i] = hq;
    g_Wql[i] = __float2half_rn(q - __half2float(hq));
    if (i < 256) g_bq[i] = (i < 128) ? bbox[i] : battn[i - 128];
}

// ===========================================================================
// Value GEMM (R15 exact): persistent 136 CTAs x 5 tiles; W resident (128KB,
// once per CTA); A fp32 -> fp16 fused staging with 2x8KB double buffer.
// ===========================================================================
#define VW_SZ     131072
#define VA_BUF    8192
#define V_CTAS    136
#define V_TILES   (MV_ / 128)     // 680
__global__ __launch_bounds__(512)
void hmma_gemm_v(const float* __restrict__ A,
                 const __half* __restrict__ Wh,
                 const float* __restrict__ bias,
                 __half* __restrict__ C,
                 const unsigned char* __restrict__ mask)
{
    extern __shared__ __align__(16) unsigned char dsm[];
    float* bias_s = (float*)(dsm + VW_SZ + 2 * VA_BUF);

    const int t    = threadIdx.x;
    const int wid  = t >> 5;
    const int lane = t & 31;
    const int wm   = wid & 3;
    const int wn   = wid >> 2;
    const uint32_t base  = smem_u32(dsm);
    const uint32_t abase = base + VW_SZ;

    if (t < 256) bias_s[t] = bias[t];

    // ---- W prologue: once per CTA ----
#pragma unroll
    for (int u = 0; u < 16; u++) {
        int f  = t + u * 512;
        int r  = f >> 5;
        int j  = f & 31;
        int ch = j >> 2;
        int cu = j & 3;
        uint32_t dst = base + ch * 16384 + r * 64 + ((cu ^ ((r >> 1) & 3)) * 16);
        CP_ASYNC16(dst, Wh + (size_t)r * 256 + j * 8);
    }
    CP_COMMIT();
    CP_WAIT0();
    __syncthreads();

    const int ar = t >> 2;
    const int au = t & 3;
    const uint32_t asw = ((au ^ ((ar >> 1) & 3)) * 16) + ar * 64;

    for (int tile = blockIdx.x; tile < V_TILES; tile += V_CTAS) {
        const int m0 = tile * 128;
        const float* asrc = A + (size_t)(m0 + ar) * 256 + au * 8;

        float acc[2][8][4];
#pragma unroll
        for (int mt = 0; mt < 2; mt++)
#pragma unroll
            for (int nt = 0; nt < 8; nt++)
#pragma unroll
                for (int i = 0; i < 4; i++) acc[mt][nt][i] = 0.f;

        float4 pa0 = *(const float4*)(asrc);
        float4 pa1 = *(const float4*)(asrc + 4);
        {
            uint4 u;
            u.x = h2_bits(__floats2half2_rn(pa0.x, pa0.y));
            u.y = h2_bits(__floats2half2_rn(pa0.z, pa0.w));
            u.z = h2_bits(__floats2half2_rn(pa1.x, pa1.y));
            u.w = h2_bits(__floats2half2_rn(pa1.z, pa1.w));
            *(uint4*)(dsm + VW_SZ + asw) = u;
        }
        __syncthreads();

        for (int ch = 0; ch < 8; ch++) {
            if (ch < 7) {
                pa0 = *(const float4*)(asrc + (ch + 1) * 32);
                pa1 = *(const float4*)(asrc + (ch + 1) * 32 + 4);
            }

            const uint32_t uA = abase + (ch & 1) * VA_BUF;
            const uint32_t uB = base + ch * 16384;

#pragma unroll
            for (int s = 0; s < 2; s++) {
                uint32_t ah[2][4];
#pragma unroll
                for (int mt = 0; mt < 2; mt++) {
                    int row  = wm * 32 + mt * 16 + (lane & 15);
                    int unit = s * 2 + (lane >> 4);
                    ldmx4(uA + row * 64 + (unit ^ ((row >> 1) & 3)) * 16,
                          ah[mt][0], ah[mt][1], ah[mt][2], ah[mt][3]);
                }
#pragma unroll
                for (int half = 0; half < 2; half++) {
                    uint32_t bh[4][2];
#pragma unroll
                    for (int p = 0; p < 2; p++) {
                        int pp   = half * 2 + p;
                        int nrow = wn * 64 + pp * 16 + (lane & 7) + (((lane >> 4) & 1) << 3);
                        int unit = s * 2 + ((lane >> 3) & 1);
                        uint32_t off = nrow * 64 + (unit ^ ((nrow >> 1) & 3)) * 16;
                        ldmx4(uB + off, bh[p*2][0], bh[p*2][1], bh[p*2+1][0], bh[p*2+1][1]);
                    }
#pragma unroll
                    for (int mt = 0; mt < 2; mt++)
#pragma unroll
                        for (int q = 0; q < 4; q++)
                            mma16816(acc[mt][half * 4 + q], ah[mt], bh[q]);
                }
            }

            if (ch < 7) {
                uint4 u;
                u.x = h2_bits(__floats2half2_rn(pa0.x, pa0.y));
                u.y = h2_bits(__floats2half2_rn(pa0.z, pa0.w));
                u.z = h2_bits(__floats2half2_rn(pa1.x, pa1.y));
                u.w = h2_bits(__floats2half2_rn(pa1.z, pa1.w));
                *(uint4*)(dsm + VW_SZ + ((ch + 1) & 1) * VA_BUF + asw) = u;
                __syncthreads();
            }
        }

        // epilogue: bias + mask, fp16 stores
        const int rw = lane >> 2;
        const int cw = (lane & 3) * 2;
#pragma unroll
        for (int mt = 0; mt < 2; mt++) {
            int r = m0 + wm * 32 + mt * 16 + rw;
            bool z0 = mask[r] != 0;
            bool z1 = mask[r + 8] != 0;
#pragma unroll
            for (int nt = 0; nt < 8; nt++) {
                int cl = wn * 64 + nt * 8 + cw;
                float b0 = bias_s[cl], b1 = bias_s[cl + 1];
                __half2 v0 = __floats2half2_rn(z0 ? 0.f : acc[mt][nt][0] + b0,
                                               z0 ? 0.f : acc[mt][nt][1] + b1);
                __half2 v1 = __floats2half2_rn(z1 ? 0.f : acc[mt][nt][2] + b0,
                                               z1 ? 0.f : acc[mt][nt][3] + b1);
                *(__half2*)(C + (size_t)r * 256 + cl)       = v0;
                *(__half2*)(C + (size_t)(r + 8) * 256 + cl) = v1;
            }
        }
        __syncthreads();   // protect A buffers before next tile overwrites
    }
}

// ===========================================================================
// fp32-A 2-pass HMMA GEMM (q-projection): C[M,256] fp32.
// ===========================================================================
__global__ __launch_bounds__(512)
void hmma_gemm_fp16(const float* __restrict__ A,
                    const __half* __restrict__ Wh,
                    const __half* __restrict__ Wl,
                    const float* __restrict__ bias,
                    float* __restrict__ C)
{
    __shared__ __align__(16) unsigned char smA [128 * 64];
    __shared__ __align__(16) unsigned char smBh[256 * 64];
    __shared__ __align__(16) unsigned char smBl[256 * 64];
    __shared__ float bias_s[256];

    const int t    = threadIdx.x;
    const int wid  = t >> 5;
    const int lane = t & 31;
    const int wm   = wid & 3;
    const int wn   = wid >> 2;
    const int m0   = blockIdx.x * 128;

    if (t < 256) bias_s[t] = bias[t];

    float acc[2][8][4];
#pragma unroll
    for (int mt = 0; mt < 2; mt++)
#pragma unroll
        for (int nt = 0; nt < 8; nt++)
#pragma unroll
            for (int i = 0; i < 4; i++) acc[mt][nt][i] = 0.f;

    const uint32_t uA  = smem_u32(smA);
    const uint32_t uBh = smem_u32(smBh);
    const uint32_t uBl = smem_u32(smBl);

    for (int k0 = 0; k0 < 256; k0 += 32) {
        {
            int r  = t >> 2;
            int c4 = t & 3;
            const float* src = A + (size_t)(m0 + r) * 256 + k0 + c4 * 8;
            float4 v0 = *(const float4*)(src);
            float4 v1 = *(const float4*)(src + 4);
            uint4 u;
            u.x = h2_bits(__floats2half2_rn(v0.x, v0.y));
            u.y = h2_bits(__floats2half2_rn(v0.z, v0.w));
            u.z = h2_bits(__floats2half2_rn(v1.x, v1.y));
            u.w = h2_bits(__floats2half2_rn(v1.z, v1.w));
            *(uint4*)(smA + r * 64 + (c4 ^ ((r >> 1) & 3)) * 16) = u;
        }
#pragma unroll
        for (int u = 0; u < 2; u++) {
            int f   = t + u * 512;
            int r   = f >> 2;
            int c16 = f & 3;
            uint32_t dst = r * 64 + (c16 ^ ((r >> 1) & 3)) * 16;
            *(uint4*)(smBh + dst) = *(const uint4*)(Wh + (size_t)r * 256 + k0 + c16 * 8);
            *(uint4*)(smBl + dst) = *(const uint4*)(Wl + (size_t)r * 256 + k0 + c16 * 8);
        }
        __syncthreads();

#pragma unroll
        for (int s = 0; s < 2; s++) {
            uint32_t ah[2][4];
#pragma unroll
            for (int mt = 0; mt < 2; mt++) {
                int row  = wm * 32 + mt * 16 + (lane & 15);
                int unit = s * 2 + (lane >> 4);
                ldmx4(uA + row * 64 + (unit ^ ((row >> 1) & 3)) * 16,
                      ah[mt][0], ah[mt][1], ah[mt][2], ah[mt][3]);
            }
#pragma unroll
            for (int half = 0; half < 2; half++) {
                uint32_t bh[4][2], bl[4][2];
#pragma unroll
                for (int p = 0; p < 2; p++) {
                    int pp   = half * 2 + p;
                    int nrow = wn * 64 + pp * 16 + (lane & 7) + (((lane >> 4) & 1) << 3);
                    int unit = s * 2 + ((lane >> 3) & 1);
                    uint32_t off = nrow * 64 + (unit ^ ((nrow >> 1) & 3)) * 16;
                    ldmx4(uBh + off, bh[p*2][0], bh[p*2][1], bh[p*2+1][0], bh[p*2+1][1]);
                    ldmx4(uBl + off, bl[p*2][0], bl[p*2][1], bl[p*2+1][0], bl[p*2+1][1]);
                }
#pragma unroll
                for (int mt = 0; mt < 2; mt++)
#pragma unroll
                    for (int q = 0; q < 4; q++) {
                        int nt = half * 4 + q;
                        mma16816(acc[mt][nt], ah[mt], bh[q]);
                        mma16816(acc[mt][nt], ah[mt], bl[q]);
                    }
            }
        }
        __syncthreads();
    }

    const int rw = lane >> 2;
    const int cw = (lane & 3) * 2;
#pragma unroll
    for (int mt = 0; mt < 2; mt++) {
        int r = m0 + wm * 32 + mt * 16 + rw;
#pragma unroll
        for (int nt = 0; nt < 8; nt++) {
            int cl = wn * 64 + nt * 8 + cw;
            float b0 = bias_s[cl], b1 = bias_s[cl + 1];
            float2 v0 = make_float2(acc[mt][nt][0] + b0, acc[mt][nt][1] + b1);
            float2 v1 = make_float2(acc[mt][nt][2] + b0, acc[mt][nt][3] + b1);
            *(float2*)(C + (size_t)r * 256 + cl)       = v0;
            *(float2*)(C + (size_t)(r + 8) * 256 + cl) = v1;
        }
    }
}

// ===========================================================================
// fp32-A single-pass HMMA GEMM (out/mout): blockIdx.y picks (A,C) pair.
// ===========================================================================
__global__ __launch_bounds__(512)
void hmma_gemm_out(const float* __restrict__ A0,
                   const float* __restrict__ A1,
                   const __half* __restrict__ Wh,
                   const float* __restrict__ bias,
                   float* __restrict__ C0,
                   float* __restrict__ C1)
{
    __shared__ __align__(16) unsigned char smA [128 * 64];
    __shared__ __align__(16) unsigned char smBh[256 * 64];
    __shared__ float bias_s[256];

    const float* A = blockIdx.y ? A1 : A0;
    float*       C = blockIdx.y ? C1 : C0;

    const int t    = threadIdx.x;
    const int wid  = t >> 5;
    const int lane = t & 31;
    const int wm   = wid & 3;
    const int wn   = wid >> 2;
    const int m0   = blockIdx.x * 128;

    if (t < 256) bias_s[t] = bias[t];

    float acc[2][8][4];
#pragma unroll
    for (int mt = 0; mt < 2; mt++)
#pragma unroll
        for (int nt = 0; nt < 8; nt++)
#pragma unroll
            for (int i = 0; i < 4; i++) acc[mt][nt][i] = 0.f;

    const uint32_t uA  = smem_u32(smA);
    const uint32_t uBh = smem_u32(smBh);

    for (int k0 = 0; k0 < 256; k0 += 32) {
        {
            int r  = t >> 2;
            int c4 = t & 3;
            const float* src = A + (size_t)(m0 + r) * 256 + k0 + c4 * 8;
            float4 v0 = *(const float4*)(src);
            float4 v1 = *(const float4*)(src + 4);
            uint4 u;
            u.x = h2_bits(__floats2half2_rn(v0.x, v0.y));
            u.y = h2_bits(__floats2half2_rn(v0.z, v0.w));
            u.z = h2_bits(__floats2half2_rn(v1.x, v1.y));
            u.w = h2_bits(__floats2half2_rn(v1.z, v1.w));
            *(uint4*)(smA + r * 64 + (c4 ^ ((r >> 1) & 3)) * 16) = u;
        }
#pragma unroll
        for (int u = 0; u < 2; u++) {
            int f   = t + u * 512;
            int r   = f >> 2;
            int c16 = f & 3;
            uint32_t dst = r * 64 + (c16 ^ ((r >> 1) & 3)) * 16;
            *(uint4*)(smBh + dst) = *(const uint4*)(Wh + (size_t)r * 256 + k0 + c16 * 8);
        }
        __syncthreads();

#pragma unroll
        for (int s = 0; s < 2; s++) {
            uint32_t ah[2][4];
#pragma unroll
            for (int mt = 0; mt < 2; mt++) {
                int row  = wm * 32 + mt * 16 + (lane & 15);
                int unit = s * 2 + (lane >> 4);
                ldmx4(uA + row * 64 + (unit ^ ((row >> 1) & 3)) * 16,
                      ah[mt][0], ah[mt][1], ah[mt][2], ah[mt][3]);
            }
#pragma unroll
            for (int half = 0; half < 2; half++) {
                uint32_t bh[4][2];
#pragma unroll
                for (int p = 0; p < 2; p++) {
                    int pp   = half * 2 + p;
                    int nrow = wn * 64 + pp * 16 + (lane & 7) + (((lane >> 4) & 1) << 3);
                    int unit = s * 2 + ((lane >> 3) & 1);
                    uint32_t off = nrow * 64 + (unit ^ ((nrow >> 1) & 3)) * 16;
                    ldmx4(uBh + off, bh[p*2][0], bh[p*2][1], bh[p*2+1][0], bh[p*2+1][1]);
                }
#pragma unroll
                for (int mt = 0; mt < 2; mt++)
#pragma unroll
                    for (int q = 0; q < 4; q++)
                        mma16816(acc[mt][half * 4 + q], ah[mt], bh[q]);
            }
        }
        __syncthreads();
    }

    const int rw = lane >> 2;
    const int cw = (lane & 3) * 2;
#pragma unroll
    for (int mt = 0; mt < 2; mt++) {
        int r = m0 + wm * 32 + mt * 16 + rw;
#pragma unroll
        for (int nt = 0; nt < 8; nt++) {
            int cl = wn * 64 + nt * 8 + cw;
            float b0 = bias_s[cl], b1 = bias_s[cl + 1];
            float2 v0 = make_float2(acc[mt][nt][0] + b0, acc[mt][nt][1] + b1);
            float2 v1 = make_float2(acc[mt][nt][2] + b0, acc[mt][nt][3] + b1);
            *(float2*)(C + (size_t)r * 256 + cl)       = v0;
            *(float2*)(C + (size_t)(r + 8) * 256 + cl) = v1;
        }
    }
}

// ---------------------------------------------------------------------------
// Sampler v4 (R15 exact): 4 samples/iteration, LDG.64 gather lanes.
// ---------------------------------------------------------------------------
__global__ __launch_bounds__(256)
void sample_kernel(const float* __restrict__ refwin,
                   float* __restrict__ awout)
{
    __shared__ float  sh_raw[128];
    __shared__ float  sh_off[128];
    __shared__ float2 sh_swlw[H_][64];
    __shared__ int4   sh_idx[512];
    __shared__ float4 sh_w[512];

    const int bq   = blockIdx.x;
    const int b    = bq >> 10;
    const int t    = threadIdx.x;
    const int h    = t >> 5;
    const int lane = t & 31;

    if (t < 128) sh_off[t] = g_qproj[(size_t)bq * 256 + t];
    else         sh_raw[t - 128] = g_qproj[(size_t)bq * 256 + t];
    __syncthreads();

    // ---- softmaxes (warp = head) ----
    float e[2];
    int   aidx[2];
#pragma unroll
    for (int tgt = 0; tgt < 2; tgt++) {
        int n = lane + 32 * tgt;
        int l = n >> 4, kk = n & 15, ii = kk >> 2, jj = kk & 3;
        int a = ((ii >> 1) << 1) + (jj >> 1);
        aidx[tgt] = a;
        e[tgt] = sh_raw[h * 16 + l * 4 + a];
    }
    awout[(size_t)bq * 512 + h * 64 + lane]      = e[0];
    awout[(size_t)bq * 512 + h * 64 + lane + 32] = e[1];

    float m = fmaxf(e[0], e[1]);
#pragma unroll
    for (int o = 16; o > 0; o >>= 1) m = fmaxf(m, __shfl_xor_sync(0xffffffffu, m, o));
    float p0 = __expf(e[0] - m), p1 = __expf(e[1] - m);
    float s = p0 + p1;
#pragma unroll
    for (int o = 16; o > 0; o >>= 1) s += __shfl_xor_sync(0xffffffffu, s, o);
    float inv = 1.f / s;

#pragma unroll
    for (int tgt = 0; tgt < 2; tgt++) {
        int a = aidx[tgt];
        float r0 = sh_raw[h * 16 + 0 + a], r1 = sh_raw[h * 16 + 4 + a];
        float r2 = sh_raw[h * 16 + 8 + a], r3 = sh_raw[h * 16 + 12 + a];
        float m4 = fmaxf(fmaxf(r0, r1), fmaxf(r2, r3));
        float s4 = __expf(r0 - m4) + __expf(r1 - m4) + __expf(r2 - m4) + __expf(r3 - m4);
        float lw = __expf(e[tgt] - m4) / s4;
        float sw = (tgt == 0 ? p0 : p1) * inv;
        sh_swlw[h][lane + 32 * tgt] = make_float2(sw, lw);
    }

    // ---- phase 1: per-sample indices (half2 units, +head offset) + weights
    const float rcx = refwin[bq * 4 + 0];
    const float rcy = refwin[bq * 4 + 1];
    const float rsx = refwin[bq * 4 + 2];
    const float rsy = refwin[bq * 4 + 3];

#pragma unroll
    for (int rep = 0; rep < 2; rep++) {
        int sidx = t + rep * 256;
        int hh = sidx >> 6;
        int n  = sidx & 63;
        int l  = n >> 4;
        int ii = (n >> 2) & 3;
        int jj = n & 3;

        float o0 = sh_off[hh * 16 + l * 4 + 0];
        float o1 = sh_off[hh * 16 + l * 4 + 1];
        float o2 = sh_off[hh * 16 + l * 4 + 2];
        float o3 = sh_off[hh * 16 + l * 4 + 3];
        float cx = rcx + o0 * 0.125f * rsx;
        float cy = rcy + o1 * 0.125f * rsy;
        float sx = fmaxf(rsx + o2 * 0.125f * rsx, 0.f);
        float sy = fmaxf(rsy + o3 * 0.125f * rsy, 0.f);

        int   Wl  = 128 >> l;
        float fW  = (float)Wl;
        int base  = (l == 0) ? 0 : (l == 1) ? 16384 : (l == 2) ? 20480 : 21504;

        float y   = (cy + ((float)ii - 1.5f) * 0.25f * sy) * fW - 0.5f;
        float x   = (cx + ((float)jj - 1.5f) * 0.25f * sx) * fW - 0.5f;
        float y0f = floorf(y);
        float x0f = floorf(x);
        float fy  = y - y0f;
        float fx  = x - x0f;
        int y0 = (int)y0f;
        int x0 = (int)x0f;
        bool vy0 = (y0 >= 0) && (y0 < Wl);
        bool vy1 = (y0 >= -1) && (y0 < Wl - 1);
        bool vx0 = (x0 >= 0) && (x0 < Wl);
        bool vx1 = (x0 >= -1) && (x0 < Wl - 1);
        int cy0 = min(max(y0, 0), Wl - 1);
        int cy1 = min(max(y0 + 1, 0), Wl - 1);
        int cx0 = min(max(x0, 0), Wl - 1);
        int cx1 = min(max(x0 + 1, 0), Wl - 1);

        int hofs = hh * 16;           // head offset in half2 units
        int4 id;
        id.x = (base + cy0 * Wl + cx0) * 128 + hofs;
        id.y = (base + cy0 * Wl + cx1) * 128 + hofs;
        id.z = (base + cy1 * Wl + cx0) * 128 + hofs;
        id.w = (base + cy1 * Wl + cx1) * 128 + hofs;
        float4 w;
        w.x = (vx0 && vy0) ? (1.f - fx) * (1.f - fy) : 0.f;
        w.y = (vx1 && vy0) ? fx * (1.f - fy) : 0.f;
        w.z = (vx0 && vy1) ? (1.f - fx) * fy : 0.f;
        w.w = (vx1 && vy1) ? fx * fy : 0.f;
        sh_idx[sidx] = id;
        sh_w[sidx]   = w;
    }
    __syncthreads();

    // ---- phase 2: 4 samples per iteration, 8B loads (4 channels/lane) ----
    const int sp2 = lane >> 3;      // sample subgroup 0..3
    const int lo  = lane & 7;       // 4-channel slot (2 half2)
    const __half2* vb2 = (const __half2*)g_v16 + (size_t)b * (L2_ * 128);

    float4 ao = make_float4(0.f, 0.f, 0.f, 0.f);
    float4 am = make_float4(0.f, 0.f, 0.f, 0.f);

#pragma unroll 4
    for (int n = 0; n < 64; n += 4) {
        int4   id = sh_idx[h * 64 + n + sp2];
        float4 w  = sh_w[h * 64 + n + sp2];

        uint2 u0 = *(const uint2*)(vb2 + id.x + lo * 2);
        uint2 u1 = *(const uint2*)(vb2 + id.y + lo * 2);
        uint2 u2 = *(const uint2*)(vb2 + id.z + lo * 2);
        uint2 u3 = *(const uint2*)(vb2 + id.w + lo * 2);

        float2 a0 = __half22float2(bits_h2(u0.x));
        float2 b0 = __half22float2(bits_h2(u0.y));
        float2 a1 = __half22float2(bits_h2(u1.x));
        float2 b1 = __half22float2(bits_h2(u1.y));
        float2 a2 = __half22float2(bits_h2(u2.x));
        float2 b2 = __half22float2(bits_h2(u2.y));
        float2 a3 = __half22float2(bits_h2(u3.x));
        float2 b3 = __half22float2(bits_h2(u3.y));

        float c0 = w.x * a0.x + w.y * a1.x + w.z * a2.x + w.w * a3.x;
        float c1 = w.x * a0.y + w.y * a1.y + w.z * a2.y + w.w * a3.y;
        float c2 = w.x * b0.x + w.y * b1.x + w.z * b2.x + w.w * b3.x;
        float c3 = w.x * b0.y + w.y * b1.y + w.z * b2.y + w.w * b3.y;

        float2 sl = sh_swlw[h][n + sp2];
        ao.x += sl.x * c0;  ao.y += sl.x * c1;
        ao.z += sl.x * c2;  ao.w += sl.x * c3;
        am.x += sl.y * c0;  am.y += sl.y * c1;
        am.z += sl.y * c2;  am.w += sl.y * c3;
    }

    // reduce across the 4 sample subgroups (xor 8, then xor 16)
#pragma unroll
    for (int o = 8; o <= 16; o <<= 1) {
        ao.x += __shfl_xor_sync(0xffffffffu, ao.x, o);
        ao.y += __shfl_xor_sync(0xffffffffu, ao.y, o);
        ao.z += __shfl_xor_sync(0xffffffffu, ao.z, o);
        ao.w += __shfl_xor_sync(0xffffffffu, ao.w, o);
        am.x += __shfl_xor_sync(0xffffffffu, am.x, o);
        am.y += __shfl_xor_sync(0xffffffffu, am.y, o);
        am.z += __shfl_xor_sync(0xffffffffu, am.z, o);
        am.w += __shfl_xor_sync(0xffffffffu, am.w, o);
    }

    if (sp2 == 0) {
        size_t od = (size_t)bq * D_ + h * HD_ + lo * 4;
        *(float4*)(g_outpre  + od) = ao;
        *(float4*)(g_moutpre + od) = am;
    }
}

// ---------------------------------------------------------------------------
extern "C" void kernel_launch(void* const* d_in, const int* in_sizes, int n_in,
                              void* d_out, int out_size)
{
    const float* query = (const float*)d_in[0];
    const float* value = (const float*)d_in[1];
    const float* refw  = (const float*)d_in[2];
    const float* Wv    = (const float*)d_in[3];
    const float* bv    = (const float*)d_in[4];
    const float* Wo    = (const float*)d_in[5];
    const float* bo    = (const float*)d_in[6];
    const float* Wbox  = (const float*)d_in[7];
    const float* bbox  = (const float*)d_in[8];
    const float* Wattn = (const float*)d_in[9];
    const float* battn = (const float*)d_in[10];
    const unsigned char* vmask = (const unsigned char*)d_in[13];

    float* out   = (float*)d_out;
    float* mout  = out  + (size_t)NQ_ * D_;
    float* awout = mout + (size_t)NQ_ * D_;

    float *pqp, *pop, *pmp, *pbq;
    __half *pv16, *pwvh, *pwoh, *pwqh, *pwql;
    cudaGetSymbolAddress((void**)&pv16,   g_v16);
    cudaGetSymbolAddress((void**)&pqp,    g_qproj);
    cudaGetSymbolAddress((void**)&pop,    g_outpre);
    cudaGetSymbolAddress((void**)&pmp,    g_moutpre);
    cudaGetSymbolAddress((void**)&pwvh,   g_Wvh);
    cudaGetSymbolAddress((void**)&pwoh,   g_Woh);
    cudaGetSymbolAddress((void**)&pwqh,   g_Wqh);
    cudaGetSymbolAddress((void**)&pwql,   g_Wql);
    cudaGetSymbolAddress((void**)&pbq,    g_bq);

    const int VSMEM = VW_SZ + 2 * VA_BUF + 1024;   // 148480
    cudaFuncSetAttribute(hmma_gemm_v,
                         cudaFuncAttributeMaxDynamicSharedMemorySize, VSMEM);

    // 0) prep: weights -> fp16
    prep_w_kernel<<<256, 256>>>(Wv, Wo, Wbox, Wattn, bbox, battn);
    // 1) fused q projection (2-pass, keeps aw output near-exact)
    hmma_gemm_fp16<<<NQ_ / 128, 512>>>(query, pwqh, pwql, pbq, pqp);
    // 2) v = value @ Wv^T + bv (persistent CTAs, R15-exact)
    hmma_gemm_v<<<V_CTAS, 512, VSMEM>>>(value, pwvh, bv, pv16, vmask);
    // 3) softmaxes + sampling (R15-exact)
    sample_kernel<<<NQ_, 256>>>(refw, awout);
    // 4) out + mout projections (single-pass Wo fp16, fused)
    hmma_gemm_out<<<dim3(NQ_ / 128, 2), 512>>>(pop, pmp, pwoh, bo, out, mout);
}